// round 3
// baseline (speedup 1.0000x reference)
#include <cuda_runtime.h>
#include <math.h>

#define TT 256
#define BB 64
#define DD 1024
#define HH 1024
#define G4 4096
#define KT 16
#define OUT_Y ((size_t)TT * BB * 2 * HH)  // 33554432

// Scratch: precomputed input projections (+biases), per dir/t/b: [4H]
__device__ float g_pre[(size_t)2 * TT * BB * G4];   // 512 MB
// Ping-pong LSTM state [dir][pp][B*H]
__device__ float g_h[2][2][BB * HH];
__device__ float g_c[2][2][BB * HH];

// ---- packed f32x2 helpers (Blackwell) ----
__device__ __forceinline__ unsigned long long pack2(float a) {
    unsigned long long r;
    asm("mov.b64 %0, {%1, %1};" : "=l"(r) : "f"(a));
    return r;
}
__device__ __forceinline__ void fma2(unsigned long long &d,
                                     unsigned long long a,
                                     unsigned long long b) {
    asm("fma.rn.f32x2 %0, %1, %2, %0;" : "+l"(d) : "l"(a), "l"(b));
}
__device__ __forceinline__ float2 unpack2(unsigned long long v) {
    float2 r;
    asm("mov.b64 {%0, %1}, %2;" : "=f"(r.x), "=f"(r.y) : "l"(v));
    return r;
}

__global__ void init_state(const float* __restrict__ h0) {
    int i = blockIdx.x * blockDim.x + threadIdx.x;  // BB*HH threads
    float v = h0[i];
    g_h[0][0][i] = v; g_h[1][0][i] = v;
    g_c[0][0][i] = v; g_c[1][0][i] = v;
}

// ============================================================
// Precompute: G[dir][t][b][j] = x[b][t][:] . W_ih_dir[j][:] + b_ih[j] + b_hh[j]
// GEMM M=16384 (b*T+t), N=4096, K=1024. Tile 128x128, KT=16, 256 thr, 8x8 micro.
// ============================================================
__global__ __launch_bounds__(256) void precompute(
    const float* __restrict__ x,
    const float* __restrict__ Wf, const float* __restrict__ Wb,
    const float* __restrict__ bihf, const float* __restrict__ bhhf,
    const float* __restrict__ bihb, const float* __restrict__ bhhb)
{
    __shared__ __align__(16) float As[KT][132];
    __shared__ __align__(16) float Bs[KT][132];

    const int dir = blockIdx.z;
    const float* __restrict__ W  = dir ? Wb   : Wf;
    const float* __restrict__ bi = dir ? bihb : bihf;
    const float* __restrict__ bh = dir ? bhhb : bhhf;

    const int tid = threadIdx.x;
    const int tx = tid & 15, ty = tid >> 4;
    const int r0 = blockIdx.y * 128;
    const int c0 = blockIdx.x * 128;

    unsigned long long acc[8][4];
#pragma unroll
    for (int i = 0; i < 8; i++)
#pragma unroll
        for (int p = 0; p < 4; p++) acc[i][p] = 0ull;

    for (int k0 = 0; k0 < DD; k0 += KT) {
#pragma unroll
        for (int it = 0; it < 2; it++) {
            int idx = it * 256 + tid;
            int row = idx >> 2, k4 = idx & 3;
            float4 v = *(const float4*)(x + (size_t)(r0 + row) * DD + k0 + k4 * 4);
            As[k4 * 4 + 0][row] = v.x; As[k4 * 4 + 1][row] = v.y;
            As[k4 * 4 + 2][row] = v.z; As[k4 * 4 + 3][row] = v.w;
        }
#pragma unroll
        for (int it = 0; it < 2; it++) {
            int idx = it * 256 + tid;
            int row = idx >> 2, k4 = idx & 3;
            float4 v = *(const float4*)(W + (size_t)(c0 + row) * DD + k0 + k4 * 4);
            Bs[k4 * 4 + 0][row] = v.x; Bs[k4 * 4 + 1][row] = v.y;
            Bs[k4 * 4 + 2][row] = v.z; Bs[k4 * 4 + 3][row] = v.w;
        }
        __syncthreads();
#pragma unroll
        for (int k = 0; k < KT; k++) {
            ulonglong2 b01 = *(const ulonglong2*)&Bs[k][tx * 8];
            ulonglong2 b23 = *(const ulonglong2*)&Bs[k][tx * 8 + 4];
#pragma unroll
            for (int i = 0; i < 8; i++) {
                unsigned long long aa = pack2(As[k][ty * 8 + i]);
                fma2(acc[i][0], aa, b01.x);
                fma2(acc[i][1], aa, b01.y);
                fma2(acc[i][2], aa, b23.x);
                fma2(acc[i][3], aa, b23.y);
            }
        }
        __syncthreads();
    }

#pragma unroll
    for (int i = 0; i < 8; i++) {
        int r = r0 + ty * 8 + i;          // r = b*T + t
        int t = r & (TT - 1);
        int b = r >> 8;
        size_t base = (((size_t)dir * TT + t) * BB + b) * G4;
#pragma unroll
        for (int p = 0; p < 4; p++) {
            float2 v = unpack2(acc[i][p]);
            int j = c0 + tx * 8 + p * 2;
            g_pre[base + j]     = v.x + bi[j]     + bh[j];
            g_pre[base + j + 1] = v.y + bi[j + 1] + bh[j + 1];
        }
    }
}

// ============================================================
// One LSTM step (both directions via blockIdx.z).
// Block tile: 32 batch rows x 32 hidden cols (x 4 gates = 128 W rows).
// B_s column c maps to gate g=c&3, j=j0+(c>>2)  => each thread's 4 cols
// are the 4 gates of one j -> fused pointwise update.
// ============================================================
__global__ __launch_bounds__(256) void lstm_step(
    int s,
    const float* __restrict__ Whf, const float* __restrict__ Whb,
    const int* __restrict__ mask, const float* __restrict__ h0,
    float* __restrict__ out)
{
    __shared__ __align__(16) float As[KT][36];
    __shared__ __align__(16) float Bs[KT][132];

    const int dir = blockIdx.z;
    const float* __restrict__ W = dir ? Whb : Whf;
    const int pp = s & 1;
    const float* __restrict__ h_in = g_h[dir][pp];
    float* __restrict__ h_out = g_h[dir][pp ^ 1];
    const float* __restrict__ c_in = g_c[dir][pp];
    float* __restrict__ c_out = g_c[dir][pp ^ 1];
    const int t = dir ? (TT - 1 - s) : s;

    const int tid = threadIdx.x;
    const int j0 = blockIdx.x * 32;
    const int b0 = blockIdx.y * 32;
    const int tcol = tid & 31, trow = tid >> 5;

    unsigned long long acc_if[4], acc_go[4];
#pragma unroll
    for (int i = 0; i < 4; i++) { acc_if[i] = 0ull; acc_go[i] = 0ull; }

    for (int k0 = 0; k0 < HH; k0 += KT) {
        if (tid < 128) {
            int row = tid >> 2, k4 = tid & 3;
            float4 v = *(const float4*)(h_in + (size_t)(b0 + row) * HH + k0 + k4 * 4);
            As[k4 * 4 + 0][row] = v.x; As[k4 * 4 + 1][row] = v.y;
            As[k4 * 4 + 2][row] = v.z; As[k4 * 4 + 3][row] = v.w;
        }
#pragma unroll
        for (int it = 0; it < 2; it++) {
            int idx = it * 256 + tid;
            int c = idx >> 2, k4 = idx & 3;
            int g = c & 3, j = c >> 2;
            float4 v = *(const float4*)(W + (size_t)(g * HH + j0 + j) * HH + k0 + k4 * 4);
            Bs[k4 * 4 + 0][c] = v.x; Bs[k4 * 4 + 1][c] = v.y;
            Bs[k4 * 4 + 2][c] = v.z; Bs[k4 * 4 + 3][c] = v.w;
        }
        __syncthreads();
#pragma unroll
        for (int k = 0; k < KT; k++) {
            ulonglong2 bv = *(const ulonglong2*)&Bs[k][tcol * 4];  // (i,f),(g,o)
#pragma unroll
            for (int i = 0; i < 4; i++) {
                unsigned long long aa = pack2(As[k][trow * 4 + i]);
                fma2(acc_if[i], aa, bv.x);
                fma2(acc_go[i], aa, bv.y);
            }
        }
        __syncthreads();
    }

    const int j = j0 + tcol;
    const size_t pbase = (((size_t)dir * TT + t) * BB) * G4;
#pragma unroll
    for (int i = 0; i < 4; i++) {
        int b = b0 + trow * 4 + i;
        float2 vif = unpack2(acc_if[i]);
        float2 vgo = unpack2(acc_go[i]);
        const float* __restrict__ pre = g_pre + pbase + (size_t)b * G4;
        float gi = vif.x + pre[j];
        float gf = vif.y + pre[HH + j];
        float gg = vgo.x + pre[2 * HH + j];
        float go = vgo.y + pre[3 * HH + j];
        float iv = 1.f / (1.f + expf(-gi));
        float fv = 1.f / (1.f + expf(-gf));
        float gv = tanhf(gg);
        float ov = 1.f / (1.f + expf(-go));
        float cn = fv * c_in[b * HH + j] + iv * gv;
        float hn = ov * tanhf(cn);
        float m = (float)mask[b * TT + t];
        float hz = h0[b * HH + j];
        hn = hn * m + hz * (1.f - m);
        cn = cn * m + hz * (1.f - m);
        h_out[b * HH + j] = hn;
        c_out[b * HH + j] = cn;
        // outputs stacked in ITERATION order for both directions (per reference)
        out[((size_t)s * BB + b) * (2 * HH) + (size_t)dir * HH + j] = hn;
        if (s == TT - 1) {
            out[OUT_Y + (size_t)b * (2 * HH) + (size_t)dir * HH + j] = hn;
            out[OUT_Y + (size_t)BB * 2 * HH + (size_t)b * (2 * HH) + (size_t)dir * HH + j] = cn;
        }
    }
}

extern "C" void kernel_launch(void* const* d_in, const int* in_sizes, int n_in,
                              void* d_out, int out_size) {
    const float* x    = (const float*)d_in[0];
    const int*   mask = (const int*)  d_in[1];
    const float* h0   = (const float*)d_in[2];
    const float* Wihf = (const float*)d_in[3];
    const float* Whhf = (const float*)d_in[4];
    const float* bihf = (const float*)d_in[5];
    const float* bhhf = (const float*)d_in[6];
    const float* Wihb = (const float*)d_in[7];
    const float* Whhb = (const float*)d_in[8];
    const float* bihb = (const float*)d_in[9];
    const float* bhhb = (const float*)d_in[10];
    float* out = (float*)d_out;

    init_state<<<(BB * HH) / 256, 256>>>(h0);
    precompute<<<dim3(32, 128, 2), 256>>>(x, Wihf, Wihb, bihf, bhhf, bihb, bhhb);
    for (int s = 0; s < TT; s++) {
        lstm_step<<<dim3(32, 2, 2), 256>>>(s, Whhf, Whhb, mask, h0, out);
    }
}

// round 4
// speedup vs baseline: 1.2481x; 1.2481x over previous
#include <cuda_runtime.h>
#include <math.h>

#define TT 256
#define BB 64
#define DD 1024
#define HH 1024
#define G4 4096
#define NC 8192            // gate columns, both dirs (2*4H)
#define KC 4               // K chunks for recurrent gemm
#define KCL 256            // K per chunk
#define OUT_Y ((size_t)TT * BB * 2 * HH)

typedef unsigned long long u64;

// Scratch
__device__ float g_pre[(size_t)2 * TT * BB * G4];   // input projections (+biases)
__device__ float g_part[KC][BB][NC];                // per-K-chunk partial gate sums
__device__ float g_h[2][2][BB * HH];                // ping-pong state
__device__ float g_c[2][2][BB * HH];

// ---- packed f32x2 helpers ----
__device__ __forceinline__ u64 mk2(float x, float y) {
    u64 r; asm("mov.b64 %0, {%1, %2};" : "=l"(r) : "f"(x), "f"(y)); return r;
}
__device__ __forceinline__ void fma2(u64 &d, u64 a, u64 b) {
    asm("fma.rn.f32x2 %0, %1, %2, %0;" : "+l"(d) : "l"(a), "l"(b));
}
__device__ __forceinline__ float fold2(u64 v) {
    float x, y; asm("mov.b64 {%0, %1}, %2;" : "=f"(x), "=f"(y) : "l"(v));
    return x + y;
}

__global__ void init_state(const float* __restrict__ h0) {
    int i = blockIdx.x * blockDim.x + threadIdx.x;  // BB*HH threads
    float v = h0[i];
    g_h[0][0][i] = v; g_h[1][0][i] = v;
    g_c[0][0][i] = v; g_c[1][0][i] = v;
}

// ============================================================
// Precompute: pre[dir][t][b][j] = x[b][t][:].W_ih[j][:] + b_ih[j] + b_hh[j]
// M=16384 rows (r=b*T+t), N=4096 per dir, K=1024.
// Block tile M64 x N256, per-thread 8x8, K-paired f32x2 accumulators.
// Thread map: ty = tid&7 (M), tx = tid>>3 (N).
// Rows: ty*2 + s2*16 + {0,1};  Cols: tx*2 + sg*64 + {0,1}.
// ============================================================
__global__ __launch_bounds__(256) void precompute(
    const float* __restrict__ x,
    const float* __restrict__ Wf, const float* __restrict__ Wb,
    const float* __restrict__ bihf, const float* __restrict__ bhhf,
    const float* __restrict__ bihb, const float* __restrict__ bhhb)
{
    __shared__ __align__(16) u64 As[8][66];    // [k-pair][row]
    __shared__ __align__(16) u64 Bs[8][258];   // [k-pair][col]

    const int dir = blockIdx.z;
    const float* __restrict__ W  = dir ? Wb   : Wf;
    const float* __restrict__ bi = dir ? bihb : bihf;
    const float* __restrict__ bh = dir ? bhhb : bhhf;

    const int tid = threadIdx.x;
    const int ty = tid & 7, tx = tid >> 3;
    const int r0 = blockIdx.y * 64;
    const int c0 = blockIdx.x * 256;

    float bsum[4][2];
#pragma unroll
    for (int sg = 0; sg < 4; sg++) {
        int j = c0 + tx * 2 + sg * 64;
        bsum[sg][0] = bi[j] + bh[j];
        bsum[sg][1] = bi[j + 1] + bh[j + 1];
    }

    u64 acc[8][8];
#pragma unroll
    for (int i = 0; i < 8; i++)
#pragma unroll
        for (int j = 0; j < 8; j++) acc[i][j] = 0ull;

    for (int k0 = 0; k0 < DD; k0 += 16) {
        {   // stage A: 64 rows x 16 k
            int row = tid >> 2, kq = tid & 3;
            float4 v = *(const float4*)(x + (size_t)(r0 + row) * DD + k0 + kq * 4);
            As[kq * 2][row]     = mk2(v.x, v.y);
            As[kq * 2 + 1][row] = mk2(v.z, v.w);
        }
#pragma unroll
        for (int it = 0; it < 4; it++) {  // stage B: 256 cols x 16 k
            int idx = it * 256 + tid;
            int col = idx >> 2, kq = idx & 3;
            float4 v = *(const float4*)(W + (size_t)(c0 + col) * DD + k0 + kq * 4);
            Bs[kq * 2][col]     = mk2(v.x, v.y);
            Bs[kq * 2 + 1][col] = mk2(v.z, v.w);
        }
        __syncthreads();
#pragma unroll
        for (int k2 = 0; k2 < 8; k2++) {
            ulonglong2 av[4], bv[4];
#pragma unroll
            for (int s2 = 0; s2 < 4; s2++)
                av[s2] = *(const ulonglong2*)&As[k2][ty * 2 + s2 * 16];
#pragma unroll
            for (int sg = 0; sg < 4; sg++)
                bv[sg] = *(const ulonglong2*)&Bs[k2][tx * 2 + sg * 64];
#pragma unroll
            for (int s2 = 0; s2 < 4; s2++)
#pragma unroll
                for (int sg = 0; sg < 4; sg++) {
                    fma2(acc[s2 * 2][sg * 2],     av[s2].x, bv[sg].x);
                    fma2(acc[s2 * 2][sg * 2 + 1], av[s2].x, bv[sg].y);
                    fma2(acc[s2 * 2 + 1][sg * 2],     av[s2].y, bv[sg].x);
                    fma2(acc[s2 * 2 + 1][sg * 2 + 1], av[s2].y, bv[sg].y);
                }
        }
        __syncthreads();
    }

#pragma unroll
    for (int s2 = 0; s2 < 4; s2++)
#pragma unroll
        for (int r01 = 0; r01 < 2; r01++) {
            int r = r0 + ty * 2 + s2 * 16 + r01;
            int t = r & (TT - 1);
            int b = r >> 8;
            float* dst = g_pre + (((size_t)dir * TT + t) * BB + b) * G4;
#pragma unroll
            for (int sg = 0; sg < 4; sg++) {
                float2 o;
                o.x = fold2(acc[s2 * 2 + r01][sg * 2])     + bsum[sg][0];
                o.y = fold2(acc[s2 * 2 + r01][sg * 2 + 1]) + bsum[sg][1];
                *(float2*)(dst + c0 + tx * 2 + sg * 64) = o;
            }
        }
}

// ============================================================
// Recurrent GEMM chunk: part[kc][b][C] = sum_{k in chunk} h[b][k] * W[C][k]
// M=64 (all batches), N=256 cols/block, Kc=256. 32 col-blocks x 4 k-chunks.
// ============================================================
__global__ __launch_bounds__(256) void step_gemm(
    int s, const float* __restrict__ Whf, const float* __restrict__ Whb)
{
    __shared__ __align__(16) u64 As[8][66];
    __shared__ __align__(16) u64 Bs[8][258];

    const int cb = blockIdx.x * 256;        // global col base (0..8191)
    const int kc = blockIdx.y;
    const int dir = cb >> 12;
    const float* __restrict__ W = dir ? Whb : Whf;
    const float* __restrict__ h_in = g_h[dir][s & 1];
    const int kb = kc * KCL;

    const int tid = threadIdx.x;
    const int ty = tid & 7, tx = tid >> 3;

    u64 acc[8][8];
#pragma unroll
    for (int i = 0; i < 8; i++)
#pragma unroll
        for (int j = 0; j < 8; j++) acc[i][j] = 0ull;

    for (int k0 = 0; k0 < KCL; k0 += 16) {
        {
            int row = tid >> 2, kq = tid & 3;
            float4 v = *(const float4*)(h_in + (size_t)row * HH + kb + k0 + kq * 4);
            As[kq * 2][row]     = mk2(v.x, v.y);
            As[kq * 2 + 1][row] = mk2(v.z, v.w);
        }
#pragma unroll
        for (int it = 0; it < 4; it++) {
            int idx = it * 256 + tid;
            int col = idx >> 2, kq = idx & 3;
            int jw = (cb + col) & (G4 - 1);
            float4 v = *(const float4*)(W + (size_t)jw * HH + kb + k0 + kq * 4);
            Bs[kq * 2][col]     = mk2(v.x, v.y);
            Bs[kq * 2 + 1][col] = mk2(v.z, v.w);
        }
        __syncthreads();
#pragma unroll
        for (int k2 = 0; k2 < 8; k2++) {
            ulonglong2 av[4], bv[4];
#pragma unroll
            for (int s2 = 0; s2 < 4; s2++)
                av[s2] = *(const ulonglong2*)&As[k2][ty * 2 + s2 * 16];
#pragma unroll
            for (int sg = 0; sg < 4; sg++)
                bv[sg] = *(const ulonglong2*)&Bs[k2][tx * 2 + sg * 64];
#pragma unroll
            for (int s2 = 0; s2 < 4; s2++)
#pragma unroll
                for (int sg = 0; sg < 4; sg++) {
                    fma2(acc[s2 * 2][sg * 2],     av[s2].x, bv[sg].x);
                    fma2(acc[s2 * 2][sg * 2 + 1], av[s2].x, bv[sg].y);
                    fma2(acc[s2 * 2 + 1][sg * 2],     av[s2].y, bv[sg].x);
                    fma2(acc[s2 * 2 + 1][sg * 2 + 1], av[s2].y, bv[sg].y);
                }
        }
        __syncthreads();
    }

#pragma unroll
    for (int s2 = 0; s2 < 4; s2++)
#pragma unroll
        for (int r01 = 0; r01 < 2; r01++) {
            int b = ty * 2 + s2 * 16 + r01;
            float* dst = g_part[kc][b];
#pragma unroll
            for (int sg = 0; sg < 4; sg++) {
                float2 o;
                o.x = fold2(acc[s2 * 2 + r01][sg * 2]);
                o.y = fold2(acc[s2 * 2 + r01][sg * 2 + 1]);
                *(float2*)(dst + cb + tx * 2 + sg * 64) = o;
            }
        }
}

// ============================================================
// Pointwise: reduce K-chunk partials + pre, LSTM cell update, masking, outputs.
// One thread per (dir, b, j). 131072 threads.
// ============================================================
__global__ __launch_bounds__(256) void step_point(
    int s, const int* __restrict__ mask, const float* __restrict__ h0,
    float* __restrict__ out)
{
    int g = blockIdx.x * 256 + threadIdx.x;
    int j = g & (HH - 1);
    int b = (g >> 10) & (BB - 1);
    int dir = g >> 16;
    int pp = s & 1;
    int t = dir ? (TT - 1 - s) : s;

    const float* __restrict__ pre = g_pre + (((size_t)dir * TT + t) * BB + b) * G4;
    const int Cb = dir * G4;

    float ga[4];
#pragma unroll
    for (int gi = 0; gi < 4; gi++) {
        int jj = gi * HH + j;
        float v = pre[jj];
#pragma unroll
        for (int kc = 0; kc < KC; kc++) v += g_part[kc][b][Cb + jj];
        ga[gi] = v;
    }

    float iv = 1.f / (1.f + expf(-ga[0]));
    float fv = 1.f / (1.f + expf(-ga[1]));
    float gv = tanhf(ga[2]);
    float ov = 1.f / (1.f + expf(-ga[3]));
    float cn = fv * g_c[dir][pp][b * HH + j] + iv * gv;
    float hn = ov * tanhf(cn);
    float m = (float)mask[b * TT + t];
    float hz = h0[b * HH + j];
    hn = hn * m + hz * (1.f - m);
    cn = cn * m + hz * (1.f - m);
    g_h[dir][pp ^ 1][b * HH + j] = hn;
    g_c[dir][pp ^ 1][b * HH + j] = cn;
    // outputs stacked in ITERATION order for both directions (per reference)
    out[((size_t)s * BB + b) * (2 * HH) + (size_t)dir * HH + j] = hn;
    if (s == TT - 1) {
        out[OUT_Y + (size_t)b * (2 * HH) + (size_t)dir * HH + j] = hn;
        out[OUT_Y + (size_t)BB * 2 * HH + (size_t)b * (2 * HH) + (size_t)dir * HH + j] = cn;
    }
}

extern "C" void kernel_launch(void* const* d_in, const int* in_sizes, int n_in,
                              void* d_out, int out_size) {
    const float* x    = (const float*)d_in[0];
    const int*   mask = (const int*)  d_in[1];
    const float* h0   = (const float*)d_in[2];
    const float* Wihf = (const float*)d_in[3];
    const float* Whhf = (const float*)d_in[4];
    const float* bihf = (const float*)d_in[5];
    const float* bhhf = (const float*)d_in[6];
    const float* Wihb = (const float*)d_in[7];
    const float* Whhb = (const float*)d_in[8];
    const float* bihb = (const float*)d_in[9];
    const float* bhhb = (const float*)d_in[10];
    float* out = (float*)d_out;

    init_state<<<(BB * HH) / 256, 256>>>(h0);
    precompute<<<dim3(16, 256, 2), 256>>>(x, Wihf, Wihb, bihf, bhhf, bihb, bhhb);
    for (int s = 0; s < TT; s++) {
        step_gemm<<<dim3(32, KC), 256>>>(s, Whhf, Whhb);
        step_point<<<512, 256>>>(s, mask, h0, out);
    }
}

// round 6
// speedup vs baseline: 2.4711x; 1.9798x over previous
#include <cuda_runtime.h>
#include <cuda_bf16.h>
#include <math.h>

#define TT 256
#define BB 64
#define HH 1024
#define G4 4096
#define OUT_Y ((size_t)TT * BB * 2 * HH)

typedef unsigned int u32;
typedef __nv_bfloat16 bf16;

// ---------------- scratch ----------------
__device__ float g_pre[(size_t)2 * TT * BB * G4];          // 512MB
__device__ float g_c[2][2][BB * HH];
__device__ bf16 g_h_hi[2][2][BB * HH], g_h_lo[2][2][BB * HH];
__device__ bf16 g_Wih_hi[(size_t)2 * G4 * HH], g_Wih_lo[(size_t)2 * G4 * HH];
__device__ bf16 g_Whh_hi[(size_t)2 * G4 * HH], g_Whh_lo[(size_t)2 * G4 * HH];
__device__ bf16 g_x_hi[(size_t)TT * BB * HH], g_x_lo[(size_t)TT * BB * HH];

// ---------------- PTX helpers (sm_80-compatible) ----------------
__device__ __forceinline__ u32 s2u(const void* p) {
    u32 a;
    asm("{ .reg .u64 t; cvta.to.shared.u64 t, %1; cvt.u32.u64 %0, t; }" : "=r"(a) : "l"(p));
    return a;
}
__device__ __forceinline__ void cpa16(u32 d, const void* s) {
    asm volatile("cp.async.cg.shared.global [%0], [%1], 16;" :: "r"(d), "l"(s));
}
#define CP_COMMIT asm volatile("cp.async.commit_group;" ::: "memory")
#define CP_WAIT1  asm volatile("cp.async.wait_group 1;" ::: "memory")

__device__ __forceinline__ void ldsm4(u32& r0, u32& r1, u32& r2, u32& r3, u32 a) {
    asm volatile("ldmatrix.sync.aligned.m8n8.x4.shared.b16 {%0,%1,%2,%3}, [%4];"
                 : "=r"(r0), "=r"(r1), "=r"(r2), "=r"(r3) : "r"(a));
}
__device__ __forceinline__ void mma16816(float* c, const u32* a, const u32* b) {
    asm volatile(
        "mma.sync.aligned.m16n8k16.row.col.f32.bf16.bf16.f32 "
        "{%0,%1,%2,%3}, {%4,%5,%6,%7}, {%8,%9}, {%0,%1,%2,%3};"
        : "+f"(c[0]), "+f"(c[1]), "+f"(c[2]), "+f"(c[3])
        : "r"(a[0]), "r"(a[1]), "r"(a[2]), "r"(a[3]), "r"(b[0]), "r"(b[1]));
}

// ---------------- split / init ----------------
__global__ void split_kernel(const float* __restrict__ src, int sel, size_t off, int n2) {
    int i = blockIdx.x * 256 + threadIdx.x;
    if (i >= n2) return;
    float2 v = ((const float2*)src)[i];
    bf16 h0b = __float2bfloat16_rn(v.x);
    bf16 h1b = __float2bfloat16_rn(v.y);
    bf16 l0b = __float2bfloat16_rn(v.x - __bfloat162float(h0b));
    bf16 l1b = __float2bfloat16_rn(v.y - __bfloat162float(h1b));
    bf16 *hi, *lo;
    if (sel == 0)      { hi = g_Wih_hi; lo = g_Wih_lo; }
    else if (sel == 1) { hi = g_Whh_hi; lo = g_Whh_lo; }
    else               { hi = g_x_hi;   lo = g_x_lo;   }
    ((__nv_bfloat162*)(hi + off))[i] = __nv_bfloat162(h0b, h1b);
    ((__nv_bfloat162*)(lo + off))[i] = __nv_bfloat162(l0b, l1b);
}

__global__ void init_state(const float* __restrict__ h0) {
    int i = blockIdx.x * blockDim.x + threadIdx.x;  // BB*HH threads
    float v = h0[i];
    bf16 hb = __float2bfloat16_rn(v);
    bf16 lb = __float2bfloat16_rn(v - __bfloat162float(hb));
    g_h_hi[0][0][i] = hb; g_h_hi[1][0][i] = hb;
    g_h_lo[0][0][i] = lb; g_h_lo[1][0][i] = lb;
    g_c[0][0][i] = v; g_c[1][0][i] = v;
}

// ============================================================
// Precompute: g_pre = x @ W_ih^T + b_ih + b_hh  (3-term bf16 split)
// Block: M=64 rows (r=b*T+t), N=128 gate cols, K=1024 (32 stages of 32).
// 8 warps: wm=wid>>2 (M32, 2 mfrags), wn=wid&3 (N32, 4 nfrags).
// smem/stage: A 128rows(hi+lo)x80B=10240, B 256rowsx80B=20480. 2 buffers.
// ============================================================
#define PC_STAGE 30720
__global__ __launch_bounds__(256) void precompute_mma(
    const float* __restrict__ bihf, const float* __restrict__ bhhf,
    const float* __restrict__ bihb, const float* __restrict__ bhhb)
{
    extern __shared__ char smem[];
    const u32 smem_u = s2u(smem);
    const int tid = threadIdx.x, lane = tid & 31, wid = tid >> 5;
    const int wm = wid >> 2, wn = wid & 3;
    const int c0 = blockIdx.x * 128, rb = blockIdx.y, dir = blockIdx.z;

    const bf16* __restrict__ Ah = g_x_hi + (size_t)rb * 64 * HH;
    const bf16* __restrict__ Al = g_x_lo + (size_t)rb * 64 * HH;
    const bf16* __restrict__ Bh = g_Wih_hi + ((size_t)dir * G4 + c0) * HH;
    const bf16* __restrict__ Bl = g_Wih_lo + ((size_t)dir * G4 + c0) * HH;

    float acc[2][4][4];
#pragma unroll
    for (int mi = 0; mi < 2; mi++)
#pragma unroll
        for (int nj = 0; nj < 4; nj++)
#pragma unroll
            for (int q = 0; q < 4; q++) acc[mi][nj][q] = 0.f;

#define PC_LOAD(st, buf) do { \
    int ko_ = (st) * 32; \
    u32 ab_ = smem_u + (buf) * PC_STAGE; \
    _Pragma("unroll") \
    for (int it = 0; it < 2; it++) { \
        int id = it * 256 + tid, row = id >> 2, c = id & 3; \
        const bf16* s_ = (row < 64 ? Ah + (size_t)row * HH \
                                   : Al + (size_t)(row - 64) * HH) + ko_ + c * 8; \
        cpa16(ab_ + row * 80 + c * 16, s_); \
    } \
    u32 bb_ = ab_ + 10240; \
    _Pragma("unroll") \
    for (int it = 0; it < 4; it++) { \
        int id = it * 256 + tid, row = id >> 2, c = id & 3; \
        int hl = row >> 7, r7 = row & 127; \
        const bf16* s_ = (hl ? Bl : Bh) + (size_t)r7 * HH + ko_ + c * 8; \
        cpa16(bb_ + row * 80 + c * 16, s_); \
    } \
} while (0)

    PC_LOAD(0, 0); CP_COMMIT;
    for (int st = 0; st < 32; st++) {
        if (st + 1 < 32) PC_LOAD(st + 1, (st + 1) & 1);
        CP_COMMIT;
        CP_WAIT1;
        __syncthreads();
        const u32 abase = smem_u + (st & 1) * PC_STAGE;
        const u32 bbase = abase + 10240;
#pragma unroll
        for (int kk = 0; kk < 2; kk++) {
            u32 a[2][2][4];
#pragma unroll
            for (int hl = 0; hl < 2; hl++)
#pragma unroll
                for (int mi = 0; mi < 2; mi++) {
                    int row = hl * 64 + wm * 32 + mi * 16 + (lane & 15);
                    ldsm4(a[hl][mi][0], a[hl][mi][1], a[hl][mi][2], a[hl][mi][3],
                          abase + row * 80 + kk * 32 + (lane >> 4) * 16);
                }
            u32 b_[2][4][2];
#pragma unroll
            for (int hl = 0; hl < 2; hl++)
#pragma unroll
                for (int nj2 = 0; nj2 < 2; nj2++) {
                    int row = hl * 128 + wn * 32 + nj2 * 16 + (lane & 7) + ((lane >> 4) << 3);
                    u32 r0, r1, r2, r3;
                    ldsm4(r0, r1, r2, r3,
                          bbase + row * 80 + kk * 32 + ((lane >> 3) & 1) * 16);
                    b_[hl][nj2 * 2][0] = r0; b_[hl][nj2 * 2][1] = r1;
                    b_[hl][nj2 * 2 + 1][0] = r2; b_[hl][nj2 * 2 + 1][1] = r3;
                }
#pragma unroll
            for (int mi = 0; mi < 2; mi++)
#pragma unroll
                for (int nj = 0; nj < 4; nj++) {
                    mma16816(acc[mi][nj], a[0][mi], b_[0][nj]);  // hi*hi
                    mma16816(acc[mi][nj], a[0][mi], b_[1][nj]);  // hi*lo
                    mma16816(acc[mi][nj], a[1][mi], b_[0][nj]);  // lo*hi
                }
        }
        __syncthreads();
    }
#undef PC_LOAD

    const float* bi = dir ? bihb : bihf;
    const float* bh = dir ? bhhb : bhhf;
#pragma unroll
    for (int nj = 0; nj < 4; nj++) {
        int n = c0 + wn * 32 + nj * 8 + (lane & 3) * 2;
        float bz0 = bi[n] + bh[n];
        float bz1 = bi[n + 1] + bh[n + 1];
#pragma unroll
        for (int mi = 0; mi < 2; mi++)
#pragma unroll
            for (int hrow = 0; hrow < 2; hrow++) {
                int m = wm * 32 + mi * 16 + (lane >> 2) + hrow * 8;
                int r = rb * 64 + m, t = r & (TT - 1), bb2 = r >> 8;
                float* dst = g_pre + (((size_t)dir * TT + t) * BB + bb2) * G4 + n;
                float2 o;
                o.x = acc[mi][nj][hrow * 2 + 0] + bz0;
                o.y = acc[mi][nj][hrow * 2 + 1] + bz1;
                *(float2*)dst = o;
            }
    }
}

// ============================================================
// Fused LSTM step: GEMM (M=64 batches, N=64 gate cols = 4 gates x 16 j,
// K=1024) + gate fold + pointwise update + output writes. One kernel/step.
// Grid (64 j-tiles, 2 dirs) = 128 CTAs.
// 8 warps: wm=wid>>1 (M16, 1 mfrag), wn=wid&1 (N32, 4 nfrags).
// smem/stage: A 128x80=10240, B 128x80=10240. 2 buffers = 40960.
// ============================================================
#define ST_STAGE 20480
__global__ __launch_bounds__(256) void step_fused(
    int s, const int* __restrict__ mask, const float* __restrict__ h0,
    float* __restrict__ out)
{
    extern __shared__ char smem[];
    const u32 smem_u = s2u(smem);
    const int tid = threadIdx.x, lane = tid & 31, wid = tid >> 5;
    const int wm = wid >> 1, wn = wid & 1;
    const int j0 = blockIdx.x * 16, dir = blockIdx.y;
    const int pp = s & 1;
    const int t = dir ? (TT - 1 - s) : s;

    const bf16* __restrict__ Ah = g_h_hi[dir][pp];
    const bf16* __restrict__ Al = g_h_lo[dir][pp];
    const bf16* __restrict__ Wh = g_Whh_hi + (size_t)dir * G4 * HH;
    const bf16* __restrict__ Wl = g_Whh_lo + (size_t)dir * G4 * HH;

    float acc[4][4];
#pragma unroll
    for (int nj = 0; nj < 4; nj++)
#pragma unroll
        for (int q = 0; q < 4; q++) acc[nj][q] = 0.f;

#define ST_LOAD(st, buf) do { \
    int ko_ = (st) * 32; \
    u32 ab_ = smem_u + (buf) * ST_STAGE; \
    _Pragma("unroll") \
    for (int it = 0; it < 2; it++) { \
        int id = it * 256 + tid, row = id >> 2, c = id & 3; \
        const bf16* s_ = (row < 64 ? Ah + (size_t)row * HH \
                                   : Al + (size_t)(row - 64) * HH) + ko_ + c * 8; \
        cpa16(ab_ + row * 80 + c * 16, s_); \
    } \
    u32 bb_ = ab_ + 10240; \
    _Pragma("unroll") \
    for (int it = 0; it < 2; it++) { \
        int id = it * 256 + tid, row = id >> 2, c = id & 3; \
        int hl = row >> 6, r6 = row & 63, grp = r6 >> 4, jj = r6 & 15; \
        const bf16* s_ = (hl ? Wl : Wh) + (size_t)(grp * HH + j0 + jj) * HH + ko_ + c * 8; \
        cpa16(bb_ + row * 80 + c * 16, s_); \
    } \
} while (0)

    ST_LOAD(0, 0); CP_COMMIT;
    for (int st = 0; st < 32; st++) {
        if (st + 1 < 32) ST_LOAD(st + 1, (st + 1) & 1);
        CP_COMMIT;
        CP_WAIT1;
        __syncthreads();
        const u32 abase = smem_u + (st & 1) * ST_STAGE;
        const u32 bbase = abase + 10240;
#pragma unroll
        for (int kk = 0; kk < 2; kk++) {
            u32 a[2][4];
#pragma unroll
            for (int hl = 0; hl < 2; hl++) {
                int row = hl * 64 + wm * 16 + (lane & 15);
                ldsm4(a[hl][0], a[hl][1], a[hl][2], a[hl][3],
                      abase + row * 80 + kk * 32 + (lane >> 4) * 16);
            }
            u32 b_[2][4][2];
#pragma unroll
            for (int hl = 0; hl < 2; hl++)
#pragma unroll
                for (int nj2 = 0; nj2 < 2; nj2++) {
                    int row = hl * 64 + wn * 32 + nj2 * 16 + (lane & 7) + ((lane >> 4) << 3);
                    u32 r0, r1, r2, r3;
                    ldsm4(r0, r1, r2, r3,
                          bbase + row * 80 + kk * 32 + ((lane >> 3) & 1) * 16);
                    b_[hl][nj2 * 2][0] = r0; b_[hl][nj2 * 2][1] = r1;
                    b_[hl][nj2 * 2 + 1][0] = r2; b_[hl][nj2 * 2 + 1][1] = r3;
                }
#pragma unroll
            for (int nj = 0; nj < 4; nj++) {
                mma16816(acc[nj], a[0], b_[0][nj]);  // hi*hi
                mma16816(acc[nj], a[0], b_[1][nj]);  // hi*lo
                mma16816(acc[nj], a[1], b_[0][nj]);  // lo*hi
            }
        }
        __syncthreads();
    }
#undef ST_LOAD

    // ---- fold accumulators into smem [64 batches][64 gate cols], stride 72 ----
    float* fold = (float*)smem;
#pragma unroll
    for (int nj = 0; nj < 4; nj++) {
        int n = wn * 32 + nj * 8 + (lane & 3) * 2;
        int m = wm * 16 + (lane >> 2);
        *(float2*)&fold[m * 72 + n]       = make_float2(acc[nj][0], acc[nj][1]);
        *(float2*)&fold[(m + 8) * 72 + n] = make_float2(acc[nj][2], acc[nj][3]);
    }
    __syncthreads();

    // ---- pointwise: 64 b x 16 jj outputs ----
#pragma unroll
    for (int it = 0; it < 4; it++) {
        int id = it * 256 + tid;
        int b = id >> 4, jj = id & 15;
        int j = j0 + jj;
        const float* pre = g_pre + (((size_t)dir * TT + t) * BB + b) * G4;
        float gi = fold[b * 72 + jj]      + pre[j];
        float gf = fold[b * 72 + 16 + jj] + pre[HH + j];
        float gg = fold[b * 72 + 32 + jj] + pre[2 * HH + j];
        float go = fold[b * 72 + 48 + jj] + pre[3 * HH + j];
        float iv = 1.f / (1.f + expf(-gi));
        float fv = 1.f / (1.f + expf(-gf));
        float gv = tanhf(gg);
        float ov = 1.f / (1.f + expf(-go));
        float cn = fv * g_c[dir][pp][b * HH + j] + iv * gv;
        float hn = ov * tanhf(cn);
        float m = (float)mask[b * TT + t];
        float hz = h0[b * HH + j];
        hn = hn * m + hz * (1.f - m);
        cn = cn * m + hz * (1.f - m);
        g_c[dir][pp ^ 1][b * HH + j] = cn;
        bf16 hh = __float2bfloat16_rn(hn);
        g_h_hi[dir][pp ^ 1][b * HH + j] = hh;
        g_h_lo[dir][pp ^ 1][b * HH + j] = __float2bfloat16_rn(hn - __bfloat162float(hh));
        // outputs stacked in ITERATION order for both directions (per reference)
        out[((size_t)s * BB + b) * (2 * HH) + (size_t)dir * HH + j] = hn;
        if (s == TT - 1) {
            out[OUT_Y + (size_t)b * (2 * HH) + (size_t)dir * HH + j] = hn;
            out[OUT_Y + (size_t)BB * 2 * HH + (size_t)b * (2 * HH) + (size_t)dir * HH + j] = cn;
        }
    }
}

// ---------------- host ----------------
extern "C" void kernel_launch(void* const* d_in, const int* in_sizes, int n_in,
                              void* d_out, int out_size) {
    const float* x    = (const float*)d_in[0];
    const int*   mask = (const int*)  d_in[1];
    const float* h0   = (const float*)d_in[2];
    const float* Wihf = (const float*)d_in[3];
    const float* Whhf = (const float*)d_in[4];
    const float* bihf = (const float*)d_in[5];
    const float* bhhf = (const float*)d_in[6];
    const float* Wihb = (const float*)d_in[7];
    const float* Whhb = (const float*)d_in[8];
    const float* bihb = (const float*)d_in[9];
    const float* bhhb = (const float*)d_in[10];
    float* out = (float*)d_out;

    static int attr_done = 0;
    cudaFuncSetAttribute(precompute_mma, cudaFuncAttributeMaxDynamicSharedMemorySize, 2 * PC_STAGE);
    cudaFuncSetAttribute(step_fused,     cudaFuncAttributeMaxDynamicSharedMemorySize, 2 * ST_STAGE);
    (void)attr_done;

    const size_t WOFF = (size_t)G4 * HH;
    split_kernel<<<8192, 256>>>(Wihf, 0, 0,    2097152);
    split_kernel<<<8192, 256>>>(Wihb, 0, WOFF, 2097152);
    split_kernel<<<8192, 256>>>(Whhf, 1, 0,    2097152);
    split_kernel<<<8192, 256>>>(Whhb, 1, WOFF, 2097152);
    split_kernel<<<32768, 256>>>(x,   2, 0,    8388608);
    init_state<<<(BB * HH) / 256, 256>>>(h0);

    precompute_mma<<<dim3(32, 256, 2), 256, 2 * PC_STAGE>>>(bihf, bhhf, bihb, bhhb);

    for (int s = 0; s < TT; s++) {
        step_fused<<<dim3(64, 2), 256, 2 * ST_STAGE>>>(s, mask, h0, out);
    }
}